// round 15
// baseline (speedup 1.0000x reference)
#include <cuda_runtime.h>
#include <cuda_fp16.h>
#include <cstdint>

// Problem constants (fixed by dataset): B=32, M=1024, E=1024, H=8, D=128
#define EDIM 1024
#define HEADS 8
#define DHEAD 128
#define MAXTOK 32768

// Scratch (__device__ globals: allocation-free rule)
__device__ __half g_aq[(size_t)MAXTOK * 1024];   // query fp16
__device__ __half g_ak[(size_t)MAXTOK * 1024];   // key fp16
__device__ __half g_av[(size_t)MAXTOK * 1024];   // value2 fp16
__device__ __half g_ao[(size_t)MAXTOK * 1024];   // attention output fp16
__device__ __half g_wq2[(size_t)EDIM * 1024];    // Wq fp16
__device__ __half g_wk2[(size_t)EDIM * 1024];    // Wk fp16
__device__ __half g_wv2[(size_t)EDIM * 1024];    // Wv fp16
__device__ __half g_wm2[(size_t)EDIM * 1024];    // Wm fp16
__device__ __half g_qp[(size_t)MAXTOK * 1024];   // Q proj (128/head)
__device__ __half g_kp[(size_t)MAXTOK * 1024];   // K proj
__device__ __half g_vp[(size_t)MAXTOK * 1024];   // V proj

// ---------------------------------------------------------------------------
// helpers (baseline PTX only: works on non-'a' sm_103 target)
// ---------------------------------------------------------------------------
__device__ __forceinline__ uint32_t s2u(const void* p) {
    uint32_t a;
    asm("{ .reg .u64 t; cvta.to.shared.u64 t, %1; cvt.u32.u64 %0, t; }"
        : "=r"(a) : "l"(p));
    return a;
}
__device__ __forceinline__ void ldsm_x4(uint32_t* r, uint32_t addr) {
    asm volatile("ldmatrix.sync.aligned.m8n8.x4.shared.b16 {%0,%1,%2,%3}, [%4];"
        : "=r"(r[0]), "=r"(r[1]), "=r"(r[2]), "=r"(r[3]) : "r"(addr));
}
__device__ __forceinline__ void ldsm_x4_t(uint32_t* r, uint32_t addr) {
    asm volatile("ldmatrix.sync.aligned.m8n8.x4.trans.shared.b16 {%0,%1,%2,%3}, [%4];"
        : "=r"(r[0]), "=r"(r[1]), "=r"(r[2]), "=r"(r[3]) : "r"(addr));
}
__device__ __forceinline__ void mma_f16(float* d, const uint32_t* a,
                                        const uint32_t* b) {
    asm volatile("mma.sync.aligned.m16n8k16.row.col.f32.f16.f16.f32 "
        "{%0,%1,%2,%3}, {%4,%5,%6,%7}, {%8,%9}, {%0,%1,%2,%3};"
        : "+f"(d[0]), "+f"(d[1]), "+f"(d[2]), "+f"(d[3])
        : "r"(a[0]), "r"(a[1]), "r"(a[2]), "r"(a[3]), "r"(b[0]), "r"(b[1]));
}
// fp16-accumulator variant (probe: potentially double-rate on legacy pipe)
__device__ __forceinline__ void mma_f16acc(uint32_t* d, const uint32_t* a,
                                           const uint32_t* b) {
    asm volatile("mma.sync.aligned.m16n8k16.row.col.f16.f16.f16.f16 "
        "{%0,%1}, {%2,%3,%4,%5}, {%6,%7}, {%0,%1};"
        : "+r"(d[0]), "+r"(d[1])
        : "r"(a[0]), "r"(a[1]), "r"(a[2]), "r"(a[3]), "r"(b[0]), "r"(b[1]));
}
__device__ __forceinline__ void cpasync16(uint32_t dst, const void* src) {
    asm volatile("cp.async.cg.shared.global [%0], [%1], 16;"
                 :: "r"(dst), "l"(src) : "memory");
}
__device__ __forceinline__ uint32_t packh2(__half lo, __half hi) {
    __half2 t; t.x = lo; t.y = hi;
    return *reinterpret_cast<uint32_t*>(&t);
}
__device__ __forceinline__ uint32_t swz(uint32_t off) {
    return off ^ ((off >> 3) & 0x70);
}

// ---------------------------------------------------------------------------
// fp32 -> fp16 plain, 8 elements per thread
// ---------------------------------------------------------------------------
__global__ void convert1h(const float* __restrict__ in,
                          __half* __restrict__ out) {
    size_t i = ((size_t)blockIdx.x * 256 + threadIdx.x) * 8;
    float4 a = *(const float4*)(in + i);
    float4 b = *(const float4*)(in + i + 4);
    *(uint32_t*)(out + i)     = packh2(__float2half(a.x), __float2half(a.y));
    *(uint32_t*)(out + i + 2) = packh2(__float2half(a.z), __float2half(a.w));
    *(uint32_t*)(out + i + 4) = packh2(__float2half(b.x), __float2half(b.y));
    *(uint32_t*)(out + i + 6) = packh2(__float2half(b.z), __float2half(b.w));
}

// ---------------------------------------------------------------------------
// HMMA fp16 GEMM: CTA 128x128, K=1024, BK=64 (128B rows), 3-stage cp.async.
// (byte-identical to R14 — proven fastest; f32 accum mandatory for K=1024)
// MODE 0: +bias -> fp32 out (final projection)
// MODE 1: +bias+CELU+GN -> plain fp16 per-head (q/k/v projections)
// ---------------------------------------------------------------------------
#define STAGE_BYTES 32768
#define GEMM_SMEM (3 * STAGE_BYTES + 2048)
#define KEL 1024
#define NCHT 16

template <int MODE>
__global__ void __launch_bounds__(256, 2) gemm_tc(
    const __half* __restrict__ Av, const __half* __restrict__ Wv,
    const float* __restrict__ bias, const float* __restrict__ gamma,
    const float* __restrict__ beta, void* __restrict__ out)
{
    constexpr bool GN = (MODE == 1);
    extern __shared__ char dsm[];
    const uint32_t sb = s2u(dsm);
    const int tid = threadIdx.x;
    const int lane = tid & 31;
    const int wrp = tid >> 5;
    const int wm = wrp & 1;
    const int wn = wrp >> 1;
    const int row0 = blockIdx.y << 7;
    const int col0 = blockIdx.x << 7;

    float* sp = (float*)(dsm + 3 * STAGE_BYTES);
    if (tid < 128) {
        sp[tid] = bias[col0 + tid];
        if (GN) {
            sp[128 + tid] = gamma[col0 + tid];
            sp[256 + tid] = beta[col0 + tid];
        }
    }

    const int gr = tid >> 3;
    const int q16 = (tid & 7) << 4;
    const size_t rstride = (size_t)KEL * 2;
    const char* Agp = (const char*)Av + (size_t)row0 * rstride + q16;
    const char* Bgp = (const char*)Wv + (size_t)col0 * rstride + q16;

    uint32_t stw[4];
#pragma unroll
    for (int l = 0; l < 4; l++)
        stw[l] = swz(((gr + (l << 5)) << 7) + q16);

    auto load_stage = [&](int c, int s) {
        uint32_t Ab = sb + s * STAGE_BYTES;
        uint32_t Bb = Ab + 16384;
#pragma unroll
        for (int l = 0; l < 4; l++) {
            int r = gr + (l << 5);
            cpasync16(Ab + stw[l], Agp + (size_t)r * rstride + (size_t)c * 128);
            cpasync16(Bb + stw[l], Bgp + (size_t)r * rstride + (size_t)c * 128);
        }
        asm volatile("cp.async.commit_group;" ::: "memory");
    };

    load_stage(0, 0);
    load_stage(1, 1);

    uint32_t asw[4];
#pragma unroll
    for (int i = 0; i < 4; i++) {
        int row = wm * 64 + i * 16 + (lane & 15);
        asw[i] = swz((row << 7) + ((lane >> 4) << 4));
    }
    uint32_t bsw[2];
#pragma unroll
    for (int j2 = 0; j2 < 2; j2++) {
        int row = wn * 32 + j2 * 16 + (lane & 7) + ((lane >> 4) << 3);
        bsw[j2] = swz((row << 7) + (((lane >> 3) & 1) << 4));
    }

    float acc[4][4][4];
#pragma unroll
    for (int i = 0; i < 4; i++)
#pragma unroll
        for (int j = 0; j < 4; j++)
#pragma unroll
            for (int t = 0; t < 4; t++) acc[i][j][t] = 0.f;

    for (int c = 0; c < NCHT; c++) {
        if (c < NCHT - 2) asm volatile("cp.async.wait_group 1;" ::: "memory");
        else              asm volatile("cp.async.wait_group 0;" ::: "memory");
        __syncthreads();
        if (c + 2 < NCHT) load_stage(c + 2, (c + 2) % 3);

        const uint32_t Ab = sb + (c % 3) * STAGE_BYTES;
        const uint32_t Bb = Ab + 16384;
#pragma unroll
        for (int ks = 0; ks < 4; ks++) {
            const uint32_t kb = ks << 5;
            uint32_t a[4][4], b[2][4];
#pragma unroll
            for (int i = 0; i < 4; i++)
                ldsm_x4(a[i], Ab + (asw[i] ^ kb));
#pragma unroll
            for (int j2 = 0; j2 < 2; j2++)
                ldsm_x4(b[j2], Bb + (bsw[j2] ^ kb));
#pragma unroll
            for (int i = 0; i < 4; i++)
#pragma unroll
                for (int j2 = 0; j2 < 2; j2++) {
                    mma_f16(acc[i][j2 * 2 + 0], a[i], &b[j2][0]);
                    mma_f16(acc[i][j2 * 2 + 1], a[i], &b[j2][2]);
                }
        }
    }
    __syncthreads();   // stage reads done before epilogue smem reuse

    // ---------------- epilogue ----------------
    const int lr = lane >> 2;
    const int lc = (lane & 3) << 1;
    const int hd = col0 >> 7;

    if (GN) {
        float* redS = (float*)dsm;
        float* redQ = redS + 512;
#pragma unroll
        for (int i = 0; i < 4; i++) {
            float s0 = 0.f, q0 = 0.f, s1 = 0.f, q1 = 0.f;
#pragma unroll
            for (int j = 0; j < 4; j++) {
                int cl = wn * 32 + j * 8 + lc;
#pragma unroll
                for (int t = 0; t < 4; t++) {
                    float v = acc[i][j][t] + sp[cl + (t & 1)];
                    v = v > 0.f ? v : 1.3f * expm1f(v * (1.0f / 1.3f));
                    acc[i][j][t] = v;
                    if (t < 2) { s0 += v; q0 += v * v; }
                    else       { s1 += v; q1 += v * v; }
                }
            }
#pragma unroll
            for (int o = 1; o < 4; o <<= 1) {
                s0 += __shfl_xor_sync(0xFFFFFFFFu, s0, o);
                q0 += __shfl_xor_sync(0xFFFFFFFFu, q0, o);
                s1 += __shfl_xor_sync(0xFFFFFFFFu, s1, o);
                q1 += __shfl_xor_sync(0xFFFFFFFFu, q1, o);
            }
            if ((lane & 3) == 0) {
                int r = wm * 64 + i * 16 + lr;
                redS[r * 4 + wn] = s0;  redQ[r * 4 + wn] = q0;
                redS[(r + 8) * 4 + wn] = s1;  redQ[(r + 8) * 4 + wn] = q1;
            }
        }
        __syncthreads();
        __half* ob = (__half*)out;
#pragma unroll
        for (int i = 0; i < 4; i++) {
            int rbase = wm * 64 + i * 16 + lr;
#pragma unroll
            for (int half_ = 0; half_ < 2; half_++) {
                int r = rbase + half_ * 8;
                float s = redS[r * 4] + redS[r * 4 + 1] + redS[r * 4 + 2] + redS[r * 4 + 3];
                float q = redQ[r * 4] + redQ[r * 4 + 1] + redQ[r * 4 + 2] + redQ[r * 4 + 3];
                float mean = s * (1.f / 128.f);
                float var = q * (1.f / 128.f) - mean * mean;
                float rs = rsqrtf(var + 1e-5f);
                int token = row0 + r;
#pragma unroll
                for (int j = 0; j < 4; j++) {
                    int cl = wn * 32 + j * 8 + lc;
                    float v0 = (acc[i][j][half_ * 2 + 0] - mean) * rs * sp[128 + cl]
                             + sp[256 + cl];
                    float v1 = (acc[i][j][half_ * 2 + 1] - mean) * rs * sp[128 + cl + 1]
                             + sp[256 + cl + 1];
                    size_t base = (size_t)token * 1024 + hd * 128 + cl;
                    *(uint32_t*)(ob + base) = packh2(__float2half(v0),
                                                     __float2half(v1));
                }
            }
        }
    } else {
        float* C = (float*)out;
#pragma unroll
        for (int i = 0; i < 4; i++) {
#pragma unroll
            for (int half_ = 0; half_ < 2; half_++) {
                int r = wm * 64 + i * 16 + lr + half_ * 8;
                float* crow = C + (size_t)(row0 + r) * EDIM + col0;
#pragma unroll
                for (int j = 0; j < 4; j++) {
                    int cl = wn * 32 + j * 8 + lc;
                    float2 ov;
                    ov.x = acc[i][j][half_ * 2 + 0] + sp[cl];
                    ov.y = acc[i][j][half_ * 2 + 1] + sp[cl + 1];
                    *(float2*)(crow + cl) = ov;
                }
            }
        }
    }
}

// ---------------------------------------------------------------------------
// Tensor-core flash attention, 2 CTAs/SM.
// S: f32-accum mma (precision-mandatory). PV: fp16-accum mma per 32-key
// chunk (2-mma chains), merged into f32 O with the alpha rescale as FFMA.
// ---------------------------------------------------------------------------
#define AT_Q   0                        // 128 x 256B = 32768
#define AT_K   32768                    // 3 stages x 8192
#define AT_V   (32768 + 24576)          // 3 stages x 8192
#define AT_MK  (AT_V + 24576)           // 3 x 128B mask
#define AT_SMEM (AT_MK + 384)

__global__ void __launch_bounds__(256, 2) attn_tc(
    const __half* __restrict__ Qp, const __half* __restrict__ Kp,
    const __half* __restrict__ Vp, const int* __restrict__ mask,
    __half* __restrict__ OB, int M)
{
    extern __shared__ char dsm[];
    const uint32_t sb = s2u(dsm);
    const int tid = threadIdx.x;
    const int lane = tid & 31;
    const int wrp = tid >> 5;
    const int qrow0 = blockIdx.x * 128;
    const int hd = blockIdx.y;
    const int b = blockIdx.z;

    const char* qg = (const char*)(Qp + (size_t)(b * M + qrow0) * 1024 + hd * 128);
    const char* kg = (const char*)(Kp + (size_t)b * M * 1024 + hd * 128);
    const char* vg = (const char*)(Vp + (size_t)b * M * 1024 + hd * 128);

#pragma unroll
    for (int l = 0; l < 8; l++) {
        int gi = tid + 256 * l;
        int row = gi >> 4, q = gi & 15;
        uint32_t off = (q >> 3) * 16384 + row * 128 + (q & 7) * 16;
        cpasync16(sb + AT_Q + swz(off), qg + (size_t)row * 2048 + q * 16);
    }

    uint32_t stw[2];
#pragma unroll
    for (int l = 0; l < 2; l++) {
        int gi = tid + 256 * l;
        int row = gi >> 4, q = gi & 15;
        stw[l] = swz((q >> 3) * 4096 + row * 128 + (q & 7) * 16);
    }

    auto load_stage = [&](int c, int s) {
        uint32_t kb = sb + AT_K + s * 8192;
        uint32_t vb = sb + AT_V + s * 8192;
#pragma unroll
        for (int l = 0; l < 2; l++) {
            int gi = tid + 256 * l;
            int row = gi >> 4, q = gi & 15;
            cpasync16(kb + stw[l], kg + (size_t)(c * 32 + row) * 2048 + q * 16);
            cpasync16(vb + stw[l], vg + (size_t)(c * 32 + row) * 2048 + q * 16);
        }
        if (tid < 8)
            cpasync16(sb + AT_MK + s * 128 + tid * 16,
                      (const char*)(mask + (size_t)b * M + c * 32) + tid * 16);
        asm volatile("cp.async.commit_group;" ::: "memory");
    };

    load_stage(0, 0);
    load_stage(1, 1);

    const uint32_t aswq = swz((wrp * 16 + (lane & 15)) * 128
                              + ((lane >> 4) << 4));
    uint32_t bswk[2];
#pragma unroll
    for (int hf = 0; hf < 2; hf++)
        bswk[hf] = swz((hf * 16 + (lane & 7) + ((lane >> 4) << 3)) * 128
                       + (((lane >> 3) & 1) << 4));
    const uint32_t vrow = ((lane & 7) + (((lane >> 3) & 1) << 3)) * 128;
    const uint32_t vcol = ((lane >> 4) << 4);
    const uint32_t swvr = swz(vrow);

    float O[16][4];
#pragma unroll
    for (int j = 0; j < 16; j++)
#pragma unroll
        for (int t = 0; t < 4; t++) O[j][t] = 0.f;
    float mi[2] = {-1e30f, -1e30f}, li[2] = {0.f, 0.f};
    const float scaling = 0.08838834764831845f;

    const int NCHA = M / 32;
    for (int c = 0; c < NCHA; c++) {
        if (c < NCHA - 2) asm volatile("cp.async.wait_group 1;" ::: "memory");
        else              asm volatile("cp.async.wait_group 0;" ::: "memory");
        __syncthreads();
        if (c + 2 < NCHA) load_stage(c + 2, (c + 2) % 3);

        const uint32_t Kb = sb + AT_K + (c % 3) * 8192;
        const uint32_t Vb = sb + AT_V + (c % 3) * 8192;
        const int* mk = (const int*)(dsm + AT_MK + (c % 3) * 128);

        // ---- S = Q . Ktile^T  (f32 accum, precision-mandatory) ----
        float cS[4][4];
#pragma unroll
        for (int t = 0; t < 4; t++)
#pragma unroll
            for (int u = 0; u < 4; u++) cS[t][u] = 0.f;
#pragma unroll
        for (int kc = 0; kc < 2; kc++) {
#pragma unroll
            for (int ks = 0; ks < 4; ks++) {
                const uint32_t kb = ks << 5;
                uint32_t a[4], bb[2][4];
                ldsm_x4(a, sb + AT_Q + kc * 16384 + (aswq ^ kb));
#pragma unroll
                for (int hf = 0; hf < 2; hf++)
                    ldsm_x4(bb[hf], Kb + kc * 4096 + (bswk[hf] ^ kb));
#pragma unroll
                for (int hf = 0; hf < 2; hf++) {
                    mma_f16(cS[hf * 2 + 0], a, &bb[hf][0]);
                    mma_f16(cS[hf * 2 + 1], a, &bb[hf][2]);
                }
            }
        }

        // ---- softmax (warp-local rows) ----
#pragma unroll
        for (int t = 0; t < 4; t++) {
            int2 mv = *(const int2*)&mk[t * 8 + ((lane & 3) << 1)];
#pragma unroll
            for (int u = 0; u < 4; u++) {
                float s = cS[t][u] * scaling;
                int mkv = (u & 1) ? mv.y : mv.x;
                cS[t][u] = (mkv == 0) ? -1e9f : s;
            }
        }
        float tmax0 = -1e30f, tmax1 = -1e30f;
#pragma unroll
        for (int t = 0; t < 4; t++) {
            tmax0 = fmaxf(tmax0, fmaxf(cS[t][0], cS[t][1]));
            tmax1 = fmaxf(tmax1, fmaxf(cS[t][2], cS[t][3]));
        }
#pragma unroll
        for (int o = 1; o < 4; o <<= 1) {
            tmax0 = fmaxf(tmax0, __shfl_xor_sync(0xFFFFFFFFu, tmax0, o));
            tmax1 = fmaxf(tmax1, __shfl_xor_sync(0xFFFFFFFFu, tmax1, o));
        }
        float mn0 = fmaxf(mi[0], tmax0), mn1 = fmaxf(mi[1], tmax1);
        float al0 = __expf(mi[0] - mn0), al1 = __expf(mi[1] - mn1);
        mi[0] = mn0; mi[1] = mn1;

        float ps0 = 0.f, ps1 = 0.f;
#pragma unroll
        for (int t = 0; t < 4; t++) {
            cS[t][0] = __expf(cS[t][0] - mn0);
            cS[t][1] = __expf(cS[t][1] - mn0);
            cS[t][2] = __expf(cS[t][2] - mn1);
            cS[t][3] = __expf(cS[t][3] - mn1);
            ps0 += cS[t][0] + cS[t][1];
            ps1 += cS[t][2] + cS[t][3];
        }
#pragma unroll
        for (int o = 1; o < 4; o <<= 1) {
            ps0 += __shfl_xor_sync(0xFFFFFFFFu, ps0, o);
            ps1 += __shfl_xor_sync(0xFFFFFFFFu, ps1, o);
        }
        li[0] = li[0] * al0 + ps0;
        li[1] = li[1] * al1 + ps1;

        // pack P into A fragments (fp16)
        uint32_t ahh[2][4];
#pragma unroll
        for (int ks = 0; ks < 2; ks++) {
#pragma unroll
            for (int sub = 0; sub < 2; sub++) {
                int t = 2 * ks + sub;
                ahh[ks][sub * 2 + 0] = packh2(__float2half(cS[t][0]),
                                              __float2half(cS[t][1]));
                ahh[ks][sub * 2 + 1] = packh2(__float2half(cS[t][2]),
                                              __float2half(cS[t][3]));
            }
        }

        // ---- chunk partial P.V in fp16 accum; merge O = O*alpha + part ----
#pragma unroll
        for (int g = 0; g < 8; g++) {
            const int vch = g >> 2;
            const uint32_t colb = (g & 3) * 32 + vcol;
            uint32_t c0[2] = {0u, 0u}, c1[2] = {0u, 0u};
#pragma unroll
            for (int ks = 0; ks < 2; ks++) {
                uint32_t bv[4];
                uint32_t ro = (uint32_t)(ks * 16) * 128;
                ldsm_x4_t(bv, Vb + vch * 4096 + ro + (swvr ^ colb));
                mma_f16acc(c0, ahh[ks], &bv[0]);
                mma_f16acc(c1, ahh[ks], &bv[2]);
            }
            float2 p00 = __half22float2(*(__half2*)&c0[0]);  // d0,d1 (row half 0)
            float2 p01 = __half22float2(*(__half2*)&c0[1]);  // d2,d3 (row half 1)
            float2 p10 = __half22float2(*(__half2*)&c1[0]);
            float2 p11 = __half22float2(*(__half2*)&c1[1]);
            O[2*g+0][0] = O[2*g+0][0] * al0 + p00.x;
            O[2*g+0][1] = O[2*g+0][1] * al0 + p00.y;
            O[2*g+0][2] = O[2*g+0][2] * al1 + p01.x;
            O[2*g+0][3] = O[2*g+0][3] * al1 + p01.y;
            O[2*g+1][0] = O[2*g+1][0] * al0 + p10.x;
            O[2*g+1][1] = O[2*g+1][1] * al0 + p10.y;
            O[2*g+1][2] = O[2*g+1][2] * al1 + p11.x;
            O[2*g+1][3] = O[2*g+1][3] * al1 + p11.y;
        }
    }

    float inv0 = 1.0f / li[0], inv1 = 1.0f / li[1];
#pragma unroll
    for (int half_ = 0; half_ < 2; half_++) {
        float inv = half_ ? inv1 : inv0;
        int token = b * M + qrow0 + wrp * 16 + (lane >> 2) + half_ * 8;
        size_t rowbase = (size_t)token * 1024 + hd * 128 + ((lane & 3) << 1);
#pragma unroll
        for (int j = 0; j < 16; j++) {
            float v0 = O[j][half_ * 2 + 0] * inv;
            float v1 = O[j][half_ * 2 + 1] * inv;
            *(uint32_t*)(OB + rowbase + j * 8) = packh2(__float2half(v0),
                                                        __float2half(v1));
        }
    }
}

// ---------------------------------------------------------------------------
// Launch: R9 topology exactly (3 side streams, 7 events — proven clean).
// ---------------------------------------------------------------------------
extern "C" void kernel_launch(void* const* d_in, const int* in_sizes, int n_in,
                              void* d_out, int out_size)
{
    const float* query  = (const float*)d_in[0];
    const float* key    = (const float*)d_in[1];
    const int*   mask   = (const int*)d_in[2];
    // d_in[3] = value1, intentionally unused (matches reference)
    const float* value2 = (const float*)d_in[4];
    const float* Wq = (const float*)d_in[5];
    const float* bq = (const float*)d_in[6];
    const float* gq = (const float*)d_in[7];
    const float* betaq = (const float*)d_in[8];
    const float* Wk = (const float*)d_in[9];
    const float* bk = (const float*)d_in[10];
    const float* gk = (const float*)d_in[11];
    const float* betak = (const float*)d_in[12];
    const float* Wv = (const float*)d_in[13];
    const float* bv = (const float*)d_in[14];
    const float* gv = (const float*)d_in[15];
    const float* betav = (const float*)d_in[16];
    const float* Wm = (const float*)d_in[17];
    const float* bm = (const float*)d_in[18];

    const int B = in_sizes[3] / EDIM;   // value1 is [B, E]
    const int Ntok = in_sizes[2];       // mask is [B, M]
    const int M = Ntok / B;

    __half *aq, *ak, *av, *ao, *wq2, *wk2, *wv2, *wm2, *qp, *kp, *vp;
    cudaGetSymbolAddress((void**)&aq, g_aq);
    cudaGetSymbolAddress((void**)&ak, g_ak);
    cudaGetSymbolAddress((void**)&av, g_av);
    cudaGetSymbolAddress((void**)&ao, g_ao);
    cudaGetSymbolAddress((void**)&wq2, g_wq2);
    cudaGetSymbolAddress((void**)&wk2, g_wk2);
    cudaGetSymbolAddress((void**)&wv2, g_wv2);
    cudaGetSymbolAddress((void**)&wm2, g_wm2);
    cudaGetSymbolAddress((void**)&qp, g_qp);
    cudaGetSymbolAddress((void**)&kp, g_kp);
    cudaGetSymbolAddress((void**)&vp, g_vp);

    static cudaStream_t s2 = nullptr, s3 = nullptr, s4 = nullptr;
    static cudaEvent_t evRoot = nullptr, evK = nullptr, evV = nullptr,
                       evW = nullptr;
    if (!s2) {
        cudaStreamCreateWithFlags(&s2, cudaStreamNonBlocking);
        cudaStreamCreateWithFlags(&s3, cudaStreamNonBlocking);
        cudaStreamCreateWithFlags(&s4, cudaStreamNonBlocking);
        cudaEventCreateWithFlags(&evRoot, cudaEventDisableTiming);
        cudaEventCreateWithFlags(&evK, cudaEventDisableTiming);
        cudaEventCreateWithFlags(&evV, cudaEventDisableTiming);
        cudaEventCreateWithFlags(&evW, cudaEventDisableTiming);
        cudaFuncSetAttribute(gemm_tc<0>,
            cudaFuncAttributeMaxDynamicSharedMemorySize, GEMM_SMEM);
        cudaFuncSetAttribute(gemm_tc<1>,
            cudaFuncAttributeMaxDynamicSharedMemorySize, GEMM_SMEM);
        cudaFuncSetAttribute(attn_tc,
            cudaFuncAttributeMaxDynamicSharedMemorySize, AT_SMEM);
    }

    dim3 blk(256);
    dim3 gg(EDIM / 128, Ntok / 128);
    const int CAW = EDIM * EDIM / 2048;   // weight convert grid (512)
    const int CAA = Ntok * EDIM / 2048;   // activation convert grid (16384)

    // ---- fork ----
    cudaEventRecord(evRoot, 0);
    cudaStreamWaitEvent(s2, evRoot, 0);
    cudaStreamWaitEvent(s3, evRoot, 0);
    cudaStreamWaitEvent(s4, evRoot, 0);

    // Q chain (capture stream)
    convert1h<<<CAW, 256>>>(Wq, wq2);
    convert1h<<<CAA, 256>>>(query, aq);
    gemm_tc<1><<<gg, blk, GEMM_SMEM>>>(aq, wq2, bq, gq, betaq, qp);

    // K chain (s2)
    convert1h<<<CAW, 256, 0, s2>>>(Wk, wk2);
    convert1h<<<CAA, 256, 0, s2>>>(key, ak);
    gemm_tc<1><<<gg, blk, GEMM_SMEM, s2>>>(ak, wk2, bk, gk, betak, kp);

    // V chain (s3)
    convert1h<<<CAW, 256, 0, s3>>>(Wv, wv2);
    convert1h<<<CAA, 256, 0, s3>>>(value2, av);
    gemm_tc<1><<<gg, blk, GEMM_SMEM, s3>>>(av, wv2, bv, gv, betav, vp);

    // Wm convert (s4) — needed only by the final GEMM
    convert1h<<<CAW, 256, 0, s4>>>(Wm, wm2);

    // ---- join ----
    cudaEventRecord(evK, s2);
    cudaStreamWaitEvent(0, evK, 0);
    cudaEventRecord(evV, s3);
    cudaStreamWaitEvent(0, evV, 0);
    cudaEventRecord(evW, s4);
    cudaStreamWaitEvent(0, evW, 0);

    dim3 ga(M / 128, HEADS, B);
    attn_tc<<<ga, blk, AT_SMEM>>>(qp, kp, vp, mask, ao, M);

    gemm_tc<0><<<gg, blk, GEMM_SMEM>>>(ao, wm2, bm, nullptr, nullptr, d_out);
}

// round 16
// speedup vs baseline: 1.0020x; 1.0020x over previous
#include <cuda_runtime.h>
#include <cuda_fp16.h>
#include <cstdint>

// Problem constants (fixed by dataset): B=32, M=1024, E=1024, H=8, D=128
#define EDIM 1024
#define HEADS 8
#define DHEAD 128
#define MAXTOK 32768

// Scratch (__device__ globals: allocation-free rule)
__device__ __half g_aq[(size_t)MAXTOK * 1024];   // query fp16
__device__ __half g_ak[(size_t)MAXTOK * 1024];   // key fp16
__device__ __half g_av[(size_t)MAXTOK * 1024];   // value2 fp16
__device__ __half g_ao[(size_t)MAXTOK * 1024];   // attention output fp16
__device__ __half g_wq2[(size_t)EDIM * 1024];    // Wq fp16
__device__ __half g_wk2[(size_t)EDIM * 1024];    // Wk fp16
__device__ __half g_wv2[(size_t)EDIM * 1024];    // Wv fp16
__device__ __half g_wm2[(size_t)EDIM * 1024];    // Wm fp16
__device__ __half g_qp[(size_t)MAXTOK * 1024];   // Q proj (128/head)
__device__ __half g_kp[(size_t)MAXTOK * 1024];   // K proj
__device__ __half g_vp[(size_t)MAXTOK * 1024];   // V proj

// ---------------------------------------------------------------------------
// helpers (baseline PTX only: works on non-'a' sm_103 target)
// ---------------------------------------------------------------------------
__device__ __forceinline__ uint32_t s2u(const void* p) {
    uint32_t a;
    asm("{ .reg .u64 t; cvta.to.shared.u64 t, %1; cvt.u32.u64 %0, t; }"
        : "=r"(a) : "l"(p));
    return a;
}
__device__ __forceinline__ void ldsm_x4(uint32_t* r, uint32_t addr) {
    asm volatile("ldmatrix.sync.aligned.m8n8.x4.shared.b16 {%0,%1,%2,%3}, [%4];"
        : "=r"(r[0]), "=r"(r[1]), "=r"(r[2]), "=r"(r[3]) : "r"(addr));
}
__device__ __forceinline__ void ldsm_x4_t(uint32_t* r, uint32_t addr) {
    asm volatile("ldmatrix.sync.aligned.m8n8.x4.trans.shared.b16 {%0,%1,%2,%3}, [%4];"
        : "=r"(r[0]), "=r"(r[1]), "=r"(r[2]), "=r"(r[3]) : "r"(addr));
}
__device__ __forceinline__ void mma_f16(float* d, const uint32_t* a,
                                        const uint32_t* b) {
    asm volatile("mma.sync.aligned.m16n8k16.row.col.f32.f16.f16.f32 "
        "{%0,%1,%2,%3}, {%4,%5,%6,%7}, {%8,%9}, {%0,%1,%2,%3};"
        : "+f"(d[0]), "+f"(d[1]), "+f"(d[2]), "+f"(d[3])
        : "r"(a[0]), "r"(a[1]), "r"(a[2]), "r"(a[3]), "r"(b[0]), "r"(b[1]));
}
__device__ __forceinline__ void cpasync16(uint32_t dst, const void* src) {
    asm volatile("cp.async.cg.shared.global [%0], [%1], 16;"
                 :: "r"(dst), "l"(src) : "memory");
}
__device__ __forceinline__ uint32_t packh2(__half lo, __half hi) {
    __half2 t; t.x = lo; t.y = hi;
    return *reinterpret_cast<uint32_t*>(&t);
}
__device__ __forceinline__ uint32_t swz(uint32_t off) {
    return off ^ ((off >> 3) & 0x70);
}

// ---------------------------------------------------------------------------
// fp32 -> fp16 plain, 8 elements per thread
// ---------------------------------------------------------------------------
__global__ void convert1h(const float* __restrict__ in,
                          __half* __restrict__ out) {
    size_t i = ((size_t)blockIdx.x * 256 + threadIdx.x) * 8;
    float4 a = *(const float4*)(in + i);
    float4 b = *(const float4*)(in + i + 4);
    *(uint32_t*)(out + i)     = packh2(__float2half(a.x), __float2half(a.y));
    *(uint32_t*)(out + i + 2) = packh2(__float2half(a.z), __float2half(a.w));
    *(uint32_t*)(out + i + 4) = packh2(__float2half(b.x), __float2half(b.y));
    *(uint32_t*)(out + i + 6) = packh2(__float2half(b.z), __float2half(b.w));
}

// ---------------------------------------------------------------------------
// HMMA fp16 GEMM: CTA 128x128, K=1024, BK=64 (128B rows), 3-stage cp.async.
// (byte-identical to R14 — proven fastest)
// MODE 0: +bias -> fp32 out (final projection)
// MODE 1: +bias+CELU+GN -> plain fp16 per-head (q/k/v projections)
// ---------------------------------------------------------------------------
#define STAGE_BYTES 32768
#define GEMM_SMEM (3 * STAGE_BYTES + 2048)
#define KEL 1024
#define NCHT 16

template <int MODE>
__global__ void __launch_bounds__(256, 2) gemm_tc(
    const __half* __restrict__ Av, const __half* __restrict__ Wv,
    const float* __restrict__ bias, const float* __restrict__ gamma,
    const float* __restrict__ beta, void* __restrict__ out)
{
    constexpr bool GN = (MODE == 1);
    extern __shared__ char dsm[];
    const uint32_t sb = s2u(dsm);
    const int tid = threadIdx.x;
    const int lane = tid & 31;
    const int wrp = tid >> 5;
    const int wm = wrp & 1;
    const int wn = wrp >> 1;
    const int row0 = blockIdx.y << 7;
    const int col0 = blockIdx.x << 7;

    float* sp = (float*)(dsm + 3 * STAGE_BYTES);
    if (tid < 128) {
        sp[tid] = bias[col0 + tid];
        if (GN) {
            sp[128 + tid] = gamma[col0 + tid];
            sp[256 + tid] = beta[col0 + tid];
        }
    }

    const int gr = tid >> 3;
    const int q16 = (tid & 7) << 4;
    const size_t rstride = (size_t)KEL * 2;
    const char* Agp = (const char*)Av + (size_t)row0 * rstride + q16;
    const char* Bgp = (const char*)Wv + (size_t)col0 * rstride + q16;

    uint32_t stw[4];
#pragma unroll
    for (int l = 0; l < 4; l++)
        stw[l] = swz(((gr + (l << 5)) << 7) + q16);

    auto load_stage = [&](int c, int s) {
        uint32_t Ab = sb + s * STAGE_BYTES;
        uint32_t Bb = Ab + 16384;
#pragma unroll
        for (int l = 0; l < 4; l++) {
            int r = gr + (l << 5);
            cpasync16(Ab + stw[l], Agp + (size_t)r * rstride + (size_t)c * 128);
            cpasync16(Bb + stw[l], Bgp + (size_t)r * rstride + (size_t)c * 128);
        }
        asm volatile("cp.async.commit_group;" ::: "memory");
    };

    load_stage(0, 0);
    load_stage(1, 1);

    uint32_t asw[4];
#pragma unroll
    for (int i = 0; i < 4; i++) {
        int row = wm * 64 + i * 16 + (lane & 15);
        asw[i] = swz((row << 7) + ((lane >> 4) << 4));
    }
    uint32_t bsw[2];
#pragma unroll
    for (int j2 = 0; j2 < 2; j2++) {
        int row = wn * 32 + j2 * 16 + (lane & 7) + ((lane >> 4) << 3);
        bsw[j2] = swz((row << 7) + (((lane >> 3) & 1) << 4));
    }

    float acc[4][4][4];
#pragma unroll
    for (int i = 0; i < 4; i++)
#pragma unroll
        for (int j = 0; j < 4; j++)
#pragma unroll
            for (int t = 0; t < 4; t++) acc[i][j][t] = 0.f;

    for (int c = 0; c < NCHT; c++) {
        if (c < NCHT - 2) asm volatile("cp.async.wait_group 1;" ::: "memory");
        else              asm volatile("cp.async.wait_group 0;" ::: "memory");
        __syncthreads();
        if (c + 2 < NCHT) load_stage(c + 2, (c + 2) % 3);

        const uint32_t Ab = sb + (c % 3) * STAGE_BYTES;
        const uint32_t Bb = Ab + 16384;
#pragma unroll
        for (int ks = 0; ks < 4; ks++) {
            const uint32_t kb = ks << 5;
            uint32_t a[4][4], b[2][4];
#pragma unroll
            for (int i = 0; i < 4; i++)
                ldsm_x4(a[i], Ab + (asw[i] ^ kb));
#pragma unroll
            for (int j2 = 0; j2 < 2; j2++)
                ldsm_x4(b[j2], Bb + (bsw[j2] ^ kb));
#pragma unroll
            for (int i = 0; i < 4; i++)
#pragma unroll
                for (int j2 = 0; j2 < 2; j2++) {
                    mma_f16(acc[i][j2 * 2 + 0], a[i], &b[j2][0]);
                    mma_f16(acc[i][j2 * 2 + 1], a[i], &b[j2][2]);
                }
        }
    }
    __syncthreads();   // stage reads done before epilogue smem reuse

    // ---------------- epilogue ----------------
    const int lr = lane >> 2;
    const int lc = (lane & 3) << 1;
    const int hd = col0 >> 7;

    if (GN) {
        float* redS = (float*)dsm;
        float* redQ = redS + 512;
#pragma unroll
        for (int i = 0; i < 4; i++) {
            float s0 = 0.f, q0 = 0.f, s1 = 0.f, q1 = 0.f;
#pragma unroll
            for (int j = 0; j < 4; j++) {
                int cl = wn * 32 + j * 8 + lc;
#pragma unroll
                for (int t = 0; t < 4; t++) {
                    float v = acc[i][j][t] + sp[cl + (t & 1)];
                    v = v > 0.f ? v : 1.3f * expm1f(v * (1.0f / 1.3f));
                    acc[i][j][t] = v;
                    if (t < 2) { s0 += v; q0 += v * v; }
                    else       { s1 += v; q1 += v * v; }
                }
            }
#pragma unroll
            for (int o = 1; o < 4; o <<= 1) {
                s0 += __shfl_xor_sync(0xFFFFFFFFu, s0, o);
                q0 += __shfl_xor_sync(0xFFFFFFFFu, q0, o);
                s1 += __shfl_xor_sync(0xFFFFFFFFu, s1, o);
                q1 += __shfl_xor_sync(0xFFFFFFFFu, q1, o);
            }
            if ((lane & 3) == 0) {
                int r = wm * 64 + i * 16 + lr;
                redS[r * 4 + wn] = s0;  redQ[r * 4 + wn] = q0;
                redS[(r + 8) * 4 + wn] = s1;  redQ[(r + 8) * 4 + wn] = q1;
            }
        }
        __syncthreads();
        __half* ob = (__half*)out;
#pragma unroll
        for (int i = 0; i < 4; i++) {
            int rbase = wm * 64 + i * 16 + lr;
#pragma unroll
            for (int half_ = 0; half_ < 2; half_++) {
                int r = rbase + half_ * 8;
                float s = redS[r * 4] + redS[r * 4 + 1] + redS[r * 4 + 2] + redS[r * 4 + 3];
                float q = redQ[r * 4] + redQ[r * 4 + 1] + redQ[r * 4 + 2] + redQ[r * 4 + 3];
                float mean = s * (1.f / 128.f);
                float var = q * (1.f / 128.f) - mean * mean;
                float rs = rsqrtf(var + 1e-5f);
                int token = row0 + r;
#pragma unroll
                for (int j = 0; j < 4; j++) {
                    int cl = wn * 32 + j * 8 + lc;
                    float v0 = (acc[i][j][half_ * 2 + 0] - mean) * rs * sp[128 + cl]
                             + sp[256 + cl];
                    float v1 = (acc[i][j][half_ * 2 + 1] - mean) * rs * sp[128 + cl + 1]
                             + sp[256 + cl + 1];
                    size_t base = (size_t)token * 1024 + hd * 128 + cl;
                    *(uint32_t*)(ob + base) = packh2(__float2half(v0),
                                                     __float2half(v1));
                }
            }
        }
    } else {
        float* C = (float*)out;
#pragma unroll
        for (int i = 0; i < 4; i++) {
#pragma unroll
            for (int half_ = 0; half_ < 2; half_++) {
                int r = wm * 64 + i * 16 + lr + half_ * 8;
                float* crow = C + (size_t)(row0 + r) * EDIM + col0;
#pragma unroll
                for (int j = 0; j < 4; j++) {
                    int cl = wn * 32 + j * 8 + lc;
                    float2 ov;
                    ov.x = acc[i][j][half_ * 2 + 0] + sp[cl];
                    ov.y = acc[i][j][half_ * 2 + 1] + sp[cl + 1];
                    *(float2*)(crow + cl) = ov;
                }
            }
        }
    }
}

// ---------------------------------------------------------------------------
// Tensor-core flash attention, plain fp16 Q/K/V, 2 CTAs/SM.
// PV reverted to f32-accum (R14). NEW: Q fragments hoisted into registers
// once before the mainloop (Q is chunk-invariant) — kills 248 ldsm/warp.
// ---------------------------------------------------------------------------
#define AT_Q   0                        // 128 x 256B = 32768
#define AT_K   32768                    // 3 stages x 8192
#define AT_V   (32768 + 24576)          // 3 stages x 8192
#define AT_MK  (AT_V + 24576)           // 3 x 128B mask
#define AT_SMEM (AT_MK + 384)

__global__ void __launch_bounds__(256, 2) attn_tc(
    const __half* __restrict__ Qp, const __half* __restrict__ Kp,
    const __half* __restrict__ Vp, const int* __restrict__ mask,
    __half* __restrict__ OB, int M)
{
    extern __shared__ char dsm[];
    const uint32_t sb = s2u(dsm);
    const int tid = threadIdx.x;
    const int lane = tid & 31;
    const int wrp = tid >> 5;
    const int qrow0 = blockIdx.x * 128;
    const int hd = blockIdx.y;
    const int b = blockIdx.z;

    const char* qg = (const char*)(Qp + (size_t)(b * M + qrow0) * 1024 + hd * 128);
    const char* kg = (const char*)(Kp + (size_t)b * M * 1024 + hd * 128);
    const char* vg = (const char*)(Vp + (size_t)b * M * 1024 + hd * 128);

#pragma unroll
    for (int l = 0; l < 8; l++) {
        int gi = tid + 256 * l;
        int row = gi >> 4, q = gi & 15;
        uint32_t off = (q >> 3) * 16384 + row * 128 + (q & 7) * 16;
        cpasync16(sb + AT_Q + swz(off), qg + (size_t)row * 2048 + q * 16);
    }
    asm volatile("cp.async.commit_group;" ::: "memory");  // Q group

    uint32_t stw[2];
#pragma unroll
    for (int l = 0; l < 2; l++) {
        int gi = tid + 256 * l;
        int row = gi >> 4, q = gi & 15;
        stw[l] = swz((q >> 3) * 4096 + row * 128 + (q & 7) * 16);
    }

    auto load_stage = [&](int c, int s) {
        uint32_t kb = sb + AT_K + s * 8192;
        uint32_t vb = sb + AT_V + s * 8192;
#pragma unroll
        for (int l = 0; l < 2; l++) {
            int gi = tid + 256 * l;
            int row = gi >> 4, q = gi & 15;
            cpasync16(kb + stw[l], kg + (size_t)(c * 32 + row) * 2048 + q * 16);
            cpasync16(vb + stw[l], vg + (size_t)(c * 32 + row) * 2048 + q * 16);
        }
        if (tid < 8)
            cpasync16(sb + AT_MK + s * 128 + tid * 16,
                      (const char*)(mask + (size_t)b * M + c * 32) + tid * 16);
        asm volatile("cp.async.commit_group;" ::: "memory");
    };

    load_stage(0, 0);
    load_stage(1, 1);

    const uint32_t aswq = swz((wrp * 16 + (lane & 15)) * 128
                              + ((lane >> 4) << 4));
    uint32_t bswk[2];
#pragma unroll
    for (int hf = 0; hf < 2; hf++)
        bswk[hf] = swz((hf * 16 + (lane & 7) + ((lane >> 4) << 3)) * 128
                       + (((lane >> 3) & 1) << 4));
    const uint32_t vrow = ((lane & 7) + (((lane >> 3) & 1) << 3)) * 128;
    const uint32_t vcol = ((lane >> 4) << 4);
    const uint32_t swvr = swz(vrow);

    // ---- hoist Q fragments: wait for Q + first K/V stage, load once ----
    asm volatile("cp.async.wait_group 1;" ::: "memory");  // Q + stage0 done
    __syncthreads();
    uint32_t qf[2][4][4];   // [kc][ks][reg]
#pragma unroll
    for (int kc = 0; kc < 2; kc++)
#pragma unroll
        for (int ks = 0; ks < 4; ks++)
            ldsm_x4(qf[kc][ks], sb + AT_Q + kc * 16384
                                + (aswq ^ ((uint32_t)ks << 5)));

    float O[16][4];
#pragma unroll
    for (int j = 0; j < 16; j++)
#pragma unroll
        for (int t = 0; t < 4; t++) O[j][t] = 0.f;
    float mi[2] = {-1e30f, -1e30f}, li[2] = {0.f, 0.f};
    const float scaling = 0.08838834764831845f;

    const int NCHA = M / 32;
    for (int c = 0; c < NCHA; c++) {
        if (c < NCHA - 2) asm volatile("cp.async.wait_group 1;" ::: "memory");
        else              asm volatile("cp.async.wait_group 0;" ::: "memory");
        __syncthreads();
        if (c + 2 < NCHA) load_stage(c + 2, (c + 2) % 3);

        const uint32_t Kb = sb + AT_K + (c % 3) * 8192;
        const uint32_t Vb = sb + AT_V + (c % 3) * 8192;
        const int* mk = (const int*)(dsm + AT_MK + (c % 3) * 128);

        // ---- S = Q . Ktile^T  (Q fragments from registers) ----
        float cS[4][4];
#pragma unroll
        for (int t = 0; t < 4; t++)
#pragma unroll
            for (int u = 0; u < 4; u++) cS[t][u] = 0.f;
#pragma unroll
        for (int kc = 0; kc < 2; kc++) {
#pragma unroll
            for (int ks = 0; ks < 4; ks++) {
                const uint32_t kb = ks << 5;
                uint32_t bb[2][4];
#pragma unroll
                for (int hf = 0; hf < 2; hf++)
                    ldsm_x4(bb[hf], Kb + kc * 4096 + (bswk[hf] ^ kb));
#pragma unroll
                for (int hf = 0; hf < 2; hf++) {
                    mma_f16(cS[hf * 2 + 0], qf[kc][ks], &bb[hf][0]);
                    mma_f16(cS[hf * 2 + 1], qf[kc][ks], &bb[hf][2]);
                }
            }
        }

        // ---- softmax (warp-local rows) ----
#pragma unroll
        for (int t = 0; t < 4; t++) {
            int2 mv = *(const int2*)&mk[t * 8 + ((lane & 3) << 1)];
#pragma unroll
            for (int u = 0; u < 4; u++) {
                float s = cS[t][u] * scaling;
                int mkv = (u & 1) ? mv.y : mv.x;
                cS[t][u] = (mkv == 0) ? -1e9f : s;
            }
        }
        float tmax0 = -1e30f, tmax1 = -1e30f;
#pragma unroll
        for (int t = 0; t < 4; t++) {
            tmax0 = fmaxf(tmax0, fmaxf(cS[t][0], cS[t][1]));
            tmax1 = fmaxf(tmax1, fmaxf(cS[t][2], cS[t][3]));
        }
#pragma unroll
        for (int o = 1; o < 4; o <<= 1) {
            tmax0 = fmaxf(tmax0, __shfl_xor_sync(0xFFFFFFFFu, tmax0, o));
            tmax1 = fmaxf(tmax1, __shfl_xor_sync(0xFFFFFFFFu, tmax1, o));
        }
        float mn0 = fmaxf(mi[0], tmax0), mn1 = fmaxf(mi[1], tmax1);
        float al0 = __expf(mi[0] - mn0), al1 = __expf(mi[1] - mn1);
        mi[0] = mn0; mi[1] = mn1;

        float ps0 = 0.f, ps1 = 0.f;
#pragma unroll
        for (int t = 0; t < 4; t++) {
            cS[t][0] = __expf(cS[t][0] - mn0);
            cS[t][1] = __expf(cS[t][1] - mn0);
            cS[t][2] = __expf(cS[t][2] - mn1);
            cS[t][3] = __expf(cS[t][3] - mn1);
            ps0 += cS[t][0] + cS[t][1];
            ps1 += cS[t][2] + cS[t][3];
        }
#pragma unroll
        for (int o = 1; o < 4; o <<= 1) {
            ps0 += __shfl_xor_sync(0xFFFFFFFFu, ps0, o);
            ps1 += __shfl_xor_sync(0xFFFFFFFFu, ps1, o);
        }
        li[0] = li[0] * al0 + ps0;
        li[1] = li[1] * al1 + ps1;
#pragma unroll
        for (int j = 0; j < 16; j++) {
            O[j][0] *= al0; O[j][1] *= al0;
            O[j][2] *= al1; O[j][3] *= al1;
        }

        // pack P into A fragments (fp16)
        uint32_t ahh[2][4];
#pragma unroll
        for (int ks = 0; ks < 2; ks++) {
#pragma unroll
            for (int sub = 0; sub < 2; sub++) {
                int t = 2 * ks + sub;
                ahh[ks][sub * 2 + 0] = packh2(__float2half(cS[t][0]),
                                              __float2half(cS[t][1]));
                ahh[ks][sub * 2 + 1] = packh2(__float2half(cS[t][2]),
                                              __float2half(cS[t][3]));
            }
        }

        // ---- O += P . V  (f32 accum — R14 path) ----
#pragma unroll
        for (int g = 0; g < 8; g++) {
            const int vch = g >> 2;
            const uint32_t colb = (g & 3) * 32 + vcol;
#pragma unroll
            for (int ks = 0; ks < 2; ks++) {
                uint32_t bv[4];
                uint32_t ro = (uint32_t)(ks * 16) * 128;
                ldsm_x4_t(bv, Vb + vch * 4096 + ro + (swvr ^ colb));
                mma_f16(O[2 * g + 0], ahh[ks], &bv[0]);
                mma_f16(O[2 * g + 1], ahh[ks], &bv[2]);
            }
        }
    }

    float inv0 = 1.0f / li[0], inv1 = 1.0f / li[1];
#pragma unroll
    for (int half_ = 0; half_ < 2; half_++) {
        float inv = half_ ? inv1 : inv0;
        int token = b * M + qrow0 + wrp * 16 + (lane >> 2) + half_ * 8;
        size_t rowbase = (size_t)token * 1024 + hd * 128 + ((lane & 3) << 1);
#pragma unroll
        for (int j = 0; j < 16; j++) {
            float v0 = O[j][half_ * 2 + 0] * inv;
            float v1 = O[j][half_ * 2 + 1] * inv;
            *(uint32_t*)(OB + rowbase + j * 8) = packh2(__float2half(v0),
                                                        __float2half(v1));
        }
    }
}

// ---------------------------------------------------------------------------
// Launch: R9 topology exactly (3 side streams, 7 events — proven clean).
// ---------------------------------------------------------------------------
extern "C" void kernel_launch(void* const* d_in, const int* in_sizes, int n_in,
                              void* d_out, int out_size)
{
    const float* query  = (const float*)d_in[0];
    const float* key    = (const float*)d_in[1];
    const int*   mask   = (const int*)d_in[2];
    // d_in[3] = value1, intentionally unused (matches reference)
    const float* value2 = (const float*)d_in[4];
    const float* Wq = (const float*)d_in[5];
    const float* bq = (const float*)d_in[6];
    const float* gq = (const float*)d_in[7];
    const float* betaq = (const float*)d_in[8];
    const float* Wk = (const float*)d_in[9];
    const float* bk = (const float*)d_in[10];
    const float* gk = (const float*)d_in[11];
    const float* betak = (const float*)d_in[12];
    const float* Wv = (const float*)d_in[13];
    const float* bv = (const float*)d_in[14];
    const float* gv = (const float*)d_in[15];
    const float* betav = (const float*)d_in[16];
    const float* Wm = (const float*)d_in[17];
    const float* bm = (const float*)d_in[18];

    const int B = in_sizes[3] / EDIM;   // value1 is [B, E]
    const int Ntok = in_sizes[2];       // mask is [B, M]
    const int M = Ntok / B;

    __half *aq, *ak, *av, *ao, *wq2, *wk2, *wv2, *wm2, *qp, *kp, *vp;
    cudaGetSymbolAddress((void**)&aq, g_aq);
    cudaGetSymbolAddress((void**)&ak, g_ak);
    cudaGetSymbolAddress((void**)&av, g_av);
    cudaGetSymbolAddress((void**)&ao, g_ao);
    cudaGetSymbolAddress((void**)&wq2, g_wq2);
    cudaGetSymbolAddress((void**)&wk2, g_wk2);
    cudaGetSymbolAddress((void**)&wv2, g_wv2);
    cudaGetSymbolAddress((void**)&wm2, g_wm2);
    cudaGetSymbolAddress((void**)&qp, g_qp);
    cudaGetSymbolAddress((void**)&kp, g_kp);
    cudaGetSymbolAddress((void**)&vp, g_vp);

    static cudaStream_t s2 = nullptr, s3 = nullptr, s4 = nullptr;
    static cudaEvent_t evRoot = nullptr, evK = nullptr, evV = nullptr,
                       evW = nullptr;
    if (!s2) {
        cudaStreamCreateWithFlags(&s2, cudaStreamNonBlocking);
        cudaStreamCreateWithFlags(&s3, cudaStreamNonBlocking);
        cudaStreamCreateWithFlags(&s4, cudaStreamNonBlocking);
        cudaEventCreateWithFlags(&evRoot, cudaEventDisableTiming);
        cudaEventCreateWithFlags(&evK, cudaEventDisableTiming);
        cudaEventCreateWithFlags(&evV, cudaEventDisableTiming);
        cudaEventCreateWithFlags(&evW, cudaEventDisableTiming);
        cudaFuncSetAttribute(gemm_tc<0>,
            cudaFuncAttributeMaxDynamicSharedMemorySize, GEMM_SMEM);
        cudaFuncSetAttribute(gemm_tc<1>,
            cudaFuncAttributeMaxDynamicSharedMemorySize, GEMM_SMEM);
        cudaFuncSetAttribute(attn_tc,
            cudaFuncAttributeMaxDynamicSharedMemorySize, AT_SMEM);
    }

    dim3 blk(256);
    dim3 gg(EDIM / 128, Ntok / 128);
    const int CAW = EDIM * EDIM / 2048;   // weight convert grid (512)
    const int CAA = Ntok * EDIM / 2048;   // activation convert grid (16384)

    // ---- fork ----
    cudaEventRecord(evRoot, 0);
    cudaStreamWaitEvent(s2, evRoot, 0);
    cudaStreamWaitEvent(s3, evRoot, 0);
    cudaStreamWaitEvent(s4, evRoot, 0);

    // Q chain (capture stream)
    convert1h<<<CAW, 256>>>(Wq, wq2);
    convert1h<<<CAA, 256>>>(query, aq);
    gemm_tc<1><<<gg, blk, GEMM_SMEM>>>(aq, wq2, bq, gq, betaq, qp);

    // K chain (s2)
    convert1h<<<CAW, 256, 0, s2>>>(Wk, wk2);
    convert1h<<<CAA, 256, 0, s2>>>(key, ak);
    gemm_tc<1><<<gg, blk, GEMM_SMEM, s2>>>(ak, wk2, bk, gk, betak, kp);

    // V chain (s3)
    convert1h<<<CAW, 256, 0, s3>>>(Wv, wv2);
    convert1h<<<CAA, 256, 0, s3>>>(value2, av);
    gemm_tc<1><<<gg, blk, GEMM_SMEM, s3>>>(av, wv2, bv, gv, betav, vp);

    // Wm convert (s4) — needed only by the final GEMM
    convert1h<<<CAW, 256, 0, s4>>>(Wm, wm2);

    // ---- join ----
    cudaEventRecord(evK, s2);
    cudaStreamWaitEvent(0, evK, 0);
    cudaEventRecord(evV, s3);
    cudaStreamWaitEvent(0, evV, 0);
    cudaEventRecord(evW, s4);
    cudaStreamWaitEvent(0, evW, 0);

    dim3 ga(M / 128, HEADS, B);
    attn_tc<<<ga, blk, AT_SMEM>>>(qp, kp, vp, mask, ao, M);

    gemm_tc<0><<<gg, blk, GEMM_SMEM>>>(ao, wm2, bm, nullptr, nullptr, d_out);
}

// round 17
// speedup vs baseline: 1.0124x; 1.0104x over previous
#include <cuda_runtime.h>
#include <cuda_fp16.h>
#include <cstdint>

// Problem constants (fixed by dataset): B=32, M=1024, E=1024, H=8, D=128
#define EDIM 1024
#define HEADS 8
#define DHEAD 128
#define MAXTOK 32768

// Scratch (__device__ globals: allocation-free rule)
__device__ __half g_aq[(size_t)MAXTOK * 1024];   // query fp16
__device__ __half g_ak[(size_t)MAXTOK * 1024];   // key fp16
__device__ __half g_av[(size_t)MAXTOK * 1024];   // value2 fp16
__device__ __half g_ao[(size_t)MAXTOK * 1024];   // attention output fp16
__device__ __half g_wq2[(size_t)EDIM * 1024];    // Wq fp16
__device__ __half g_wk2[(size_t)EDIM * 1024];    // Wk fp16
__device__ __half g_wv2[(size_t)EDIM * 1024];    // Wv fp16
__device__ __half g_wm2[(size_t)EDIM * 1024];    // Wm fp16
__device__ __half g_qp[(size_t)MAXTOK * 1024];   // Q proj (128/head)
__device__ __half g_kp[(size_t)MAXTOK * 1024];   // K proj
__device__ __half g_vp[(size_t)MAXTOK * 1024];   // V proj

// ---------------------------------------------------------------------------
// helpers (baseline PTX only: works on non-'a' sm_103 target)
// ---------------------------------------------------------------------------
__device__ __forceinline__ uint32_t s2u(const void* p) {
    uint32_t a;
    asm("{ .reg .u64 t; cvta.to.shared.u64 t, %1; cvt.u32.u64 %0, t; }"
        : "=r"(a) : "l"(p));
    return a;
}
__device__ __forceinline__ void ldsm_x4(uint32_t* r, uint32_t addr) {
    asm volatile("ldmatrix.sync.aligned.m8n8.x4.shared.b16 {%0,%1,%2,%3}, [%4];"
        : "=r"(r[0]), "=r"(r[1]), "=r"(r[2]), "=r"(r[3]) : "r"(addr));
}
__device__ __forceinline__ void ldsm_x4_t(uint32_t* r, uint32_t addr) {
    asm volatile("ldmatrix.sync.aligned.m8n8.x4.trans.shared.b16 {%0,%1,%2,%3}, [%4];"
        : "=r"(r[0]), "=r"(r[1]), "=r"(r[2]), "=r"(r[3]) : "r"(addr));
}
__device__ __forceinline__ void mma_f16(float* d, const uint32_t* a,
                                        const uint32_t* b) {
    asm volatile("mma.sync.aligned.m16n8k16.row.col.f32.f16.f16.f32 "
        "{%0,%1,%2,%3}, {%4,%5,%6,%7}, {%8,%9}, {%0,%1,%2,%3};"
        : "+f"(d[0]), "+f"(d[1]), "+f"(d[2]), "+f"(d[3])
        : "r"(a[0]), "r"(a[1]), "r"(a[2]), "r"(a[3]), "r"(b[0]), "r"(b[1]));
}
__device__ __forceinline__ void cpasync16(uint32_t dst, const void* src) {
    asm volatile("cp.async.cg.shared.global [%0], [%1], 16;"
                 :: "r"(dst), "l"(src) : "memory");
}
__device__ __forceinline__ uint32_t packh2(__half lo, __half hi) {
    __half2 t; t.x = lo; t.y = hi;
    return *reinterpret_cast<uint32_t*>(&t);
}
__device__ __forceinline__ uint32_t swz(uint32_t off) {
    return off ^ ((off >> 3) & 0x70);
}

// ---------------------------------------------------------------------------
// fp32 -> fp16 plain, 8 elements per thread
// ---------------------------------------------------------------------------
__global__ void convert1h(const float* __restrict__ in,
                          __half* __restrict__ out) {
    size_t i = ((size_t)blockIdx.x * 256 + threadIdx.x) * 8;
    float4 a = *(const float4*)(in + i);
    float4 b = *(const float4*)(in + i + 4);
    *(uint32_t*)(out + i)     = packh2(__float2half(a.x), __float2half(a.y));
    *(uint32_t*)(out + i + 2) = packh2(__float2half(a.z), __float2half(a.w));
    *(uint32_t*)(out + i + 4) = packh2(__float2half(b.x), __float2half(b.y));
    *(uint32_t*)(out + i + 6) = packh2(__float2half(b.z), __float2half(b.w));
}

// ---------------------------------------------------------------------------
// HMMA fp16 GEMM: CTA 128x128, K=1024, BK=64 (128B rows), 3-stage cp.async.
// Single barrier per chunk; pre-swizzled fragment bases (swz(base+kb) ==
// swz(base)^kb identity). Proven fastest configuration (R14).
// MODE 0: +bias -> fp32 out (final projection)
// MODE 1: +bias+CELU+GN -> plain fp16 per-head (q/k/v projections)
// ---------------------------------------------------------------------------
#define STAGE_BYTES 32768
#define GEMM_SMEM (3 * STAGE_BYTES + 2048)
#define KEL 1024
#define NCHT 16

template <int MODE>
__global__ void __launch_bounds__(256, 2) gemm_tc(
    const __half* __restrict__ Av, const __half* __restrict__ Wv,
    const float* __restrict__ bias, const float* __restrict__ gamma,
    const float* __restrict__ beta, void* __restrict__ out)
{
    constexpr bool GN = (MODE == 1);
    extern __shared__ char dsm[];
    const uint32_t sb = s2u(dsm);
    const int tid = threadIdx.x;
    const int lane = tid & 31;
    const int wrp = tid >> 5;
    const int wm = wrp & 1;
    const int wn = wrp >> 1;
    const int row0 = blockIdx.y << 7;
    const int col0 = blockIdx.x << 7;

    float* sp = (float*)(dsm + 3 * STAGE_BYTES);
    if (tid < 128) {
        sp[tid] = bias[col0 + tid];
        if (GN) {
            sp[128 + tid] = gamma[col0 + tid];
            sp[256 + tid] = beta[col0 + tid];
        }
    }

    const int gr = tid >> 3;
    const int q16 = (tid & 7) << 4;
    const size_t rstride = (size_t)KEL * 2;
    const char* Agp = (const char*)Av + (size_t)row0 * rstride + q16;
    const char* Bgp = (const char*)Wv + (size_t)col0 * rstride + q16;

    uint32_t stw[4];
#pragma unroll
    for (int l = 0; l < 4; l++)
        stw[l] = swz(((gr + (l << 5)) << 7) + q16);

    auto load_stage = [&](int c, int s) {
        uint32_t Ab = sb + s * STAGE_BYTES;
        uint32_t Bb = Ab + 16384;
#pragma unroll
        for (int l = 0; l < 4; l++) {
            int r = gr + (l << 5);
            cpasync16(Ab + stw[l], Agp + (size_t)r * rstride + (size_t)c * 128);
            cpasync16(Bb + stw[l], Bgp + (size_t)r * rstride + (size_t)c * 128);
        }
        asm volatile("cp.async.commit_group;" ::: "memory");
    };

    load_stage(0, 0);
    load_stage(1, 1);

    uint32_t asw[4];
#pragma unroll
    for (int i = 0; i < 4; i++) {
        int row = wm * 64 + i * 16 + (lane & 15);
        asw[i] = swz((row << 7) + ((lane >> 4) << 4));
    }
    uint32_t bsw[2];
#pragma unroll
    for (int j2 = 0; j2 < 2; j2++) {
        int row = wn * 32 + j2 * 16 + (lane & 7) + ((lane >> 4) << 3);
        bsw[j2] = swz((row << 7) + (((lane >> 3) & 1) << 4));
    }

    float acc[4][4][4];
#pragma unroll
    for (int i = 0; i < 4; i++)
#pragma unroll
        for (int j = 0; j < 4; j++)
#pragma unroll
            for (int t = 0; t < 4; t++) acc[i][j][t] = 0.f;

    for (int c = 0; c < NCHT; c++) {
        if (c < NCHT - 2) asm volatile("cp.async.wait_group 1;" ::: "memory");
        else              asm volatile("cp.async.wait_group 0;" ::: "memory");
        __syncthreads();
        if (c + 2 < NCHT) load_stage(c + 2, (c + 2) % 3);

        const uint32_t Ab = sb + (c % 3) * STAGE_BYTES;
        const uint32_t Bb = Ab + 16384;
#pragma unroll
        for (int ks = 0; ks < 4; ks++) {
            const uint32_t kb = ks << 5;
            uint32_t a[4][4], b[2][4];
#pragma unroll
            for (int i = 0; i < 4; i++)
                ldsm_x4(a[i], Ab + (asw[i] ^ kb));
#pragma unroll
            for (int j2 = 0; j2 < 2; j2++)
                ldsm_x4(b[j2], Bb + (bsw[j2] ^ kb));
#pragma unroll
            for (int i = 0; i < 4; i++)
#pragma unroll
                for (int j2 = 0; j2 < 2; j2++) {
                    mma_f16(acc[i][j2 * 2 + 0], a[i], &b[j2][0]);
                    mma_f16(acc[i][j2 * 2 + 1], a[i], &b[j2][2]);
                }
        }
    }
    __syncthreads();   // stage reads done before epilogue smem reuse

    // ---------------- epilogue ----------------
    const int lr = lane >> 2;
    const int lc = (lane & 3) << 1;
    const int hd = col0 >> 7;

    if (GN) {
        float* redS = (float*)dsm;
        float* redQ = redS + 512;
#pragma unroll
        for (int i = 0; i < 4; i++) {
            float s0 = 0.f, q0 = 0.f, s1 = 0.f, q1 = 0.f;
#pragma unroll
            for (int j = 0; j < 4; j++) {
                int cl = wn * 32 + j * 8 + lc;
#pragma unroll
                for (int t = 0; t < 4; t++) {
                    float v = acc[i][j][t] + sp[cl + (t & 1)];
                    v = v > 0.f ? v : 1.3f * expm1f(v * (1.0f / 1.3f));
                    acc[i][j][t] = v;
                    if (t < 2) { s0 += v; q0 += v * v; }
                    else       { s1 += v; q1 += v * v; }
                }
            }
#pragma unroll
            for (int o = 1; o < 4; o <<= 1) {
                s0 += __shfl_xor_sync(0xFFFFFFFFu, s0, o);
                q0 += __shfl_xor_sync(0xFFFFFFFFu, q0, o);
                s1 += __shfl_xor_sync(0xFFFFFFFFu, s1, o);
                q1 += __shfl_xor_sync(0xFFFFFFFFu, q1, o);
            }
            if ((lane & 3) == 0) {
                int r = wm * 64 + i * 16 + lr;
                redS[r * 4 + wn] = s0;  redQ[r * 4 + wn] = q0;
                redS[(r + 8) * 4 + wn] = s1;  redQ[(r + 8) * 4 + wn] = q1;
            }
        }
        __syncthreads();
        __half* ob = (__half*)out;
#pragma unroll
        for (int i = 0; i < 4; i++) {
            int rbase = wm * 64 + i * 16 + lr;
#pragma unroll
            for (int half_ = 0; half_ < 2; half_++) {
                int r = rbase + half_ * 8;
                float s = redS[r * 4] + redS[r * 4 + 1] + redS[r * 4 + 2] + redS[r * 4 + 3];
                float q = redQ[r * 4] + redQ[r * 4 + 1] + redQ[r * 4 + 2] + redQ[r * 4 + 3];
                float mean = s * (1.f / 128.f);
                float var = q * (1.f / 128.f) - mean * mean;
                float rs = rsqrtf(var + 1e-5f);
                int token = row0 + r;
#pragma unroll
                for (int j = 0; j < 4; j++) {
                    int cl = wn * 32 + j * 8 + lc;
                    float v0 = (acc[i][j][half_ * 2 + 0] - mean) * rs * sp[128 + cl]
                             + sp[256 + cl];
                    float v1 = (acc[i][j][half_ * 2 + 1] - mean) * rs * sp[128 + cl + 1]
                             + sp[256 + cl + 1];
                    size_t base = (size_t)token * 1024 + hd * 128 + cl;
                    *(uint32_t*)(ob + base) = packh2(__float2half(v0),
                                                     __float2half(v1));
                }
            }
        }
    } else {
        float* C = (float*)out;
#pragma unroll
        for (int i = 0; i < 4; i++) {
#pragma unroll
            for (int half_ = 0; half_ < 2; half_++) {
                int r = wm * 64 + i * 16 + lr + half_ * 8;
                float* crow = C + (size_t)(row0 + r) * EDIM + col0;
#pragma unroll
                for (int j = 0; j < 4; j++) {
                    int cl = wn * 32 + j * 8 + lc;
                    float2 ov;
                    ov.x = acc[i][j][half_ * 2 + 0] + sp[cl];
                    ov.y = acc[i][j][half_ * 2 + 1] + sp[cl + 1];
                    *(float2*)(crow + cl) = ov;
                }
            }
        }
    }
}

// ---------------------------------------------------------------------------
// Tensor-core flash attention, plain fp16 Q/K/V, 2 CTAs/SM. (R14 exactly:
// f32-accum PV, Q fragments from smem each chunk — proven fastest balance.)
// ---------------------------------------------------------------------------
#define AT_Q   0                        // 128 x 256B = 32768
#define AT_K   32768                    // 3 stages x 8192
#define AT_V   (32768 + 24576)          // 3 stages x 8192
#define AT_MK  (AT_V + 24576)           // 3 x 128B mask
#define AT_SMEM (AT_MK + 384)

__global__ void __launch_bounds__(256, 2) attn_tc(
    const __half* __restrict__ Qp, const __half* __restrict__ Kp,
    const __half* __restrict__ Vp, const int* __restrict__ mask,
    __half* __restrict__ OB, int M)
{
    extern __shared__ char dsm[];
    const uint32_t sb = s2u(dsm);
    const int tid = threadIdx.x;
    const int lane = tid & 31;
    const int wrp = tid >> 5;
    const int qrow0 = blockIdx.x * 128;
    const int hd = blockIdx.y;
    const int b = blockIdx.z;

    const char* qg = (const char*)(Qp + (size_t)(b * M + qrow0) * 1024 + hd * 128);
    const char* kg = (const char*)(Kp + (size_t)b * M * 1024 + hd * 128);
    const char* vg = (const char*)(Vp + (size_t)b * M * 1024 + hd * 128);

#pragma unroll
    for (int l = 0; l < 8; l++) {
        int gi = tid + 256 * l;
        int row = gi >> 4, q = gi & 15;
        uint32_t off = (q >> 3) * 16384 + row * 128 + (q & 7) * 16;
        cpasync16(sb + AT_Q + swz(off), qg + (size_t)row * 2048 + q * 16);
    }

    uint32_t stw[2];
#pragma unroll
    for (int l = 0; l < 2; l++) {
        int gi = tid + 256 * l;
        int row = gi >> 4, q = gi & 15;
        stw[l] = swz((q >> 3) * 4096 + row * 128 + (q & 7) * 16);
    }

    auto load_stage = [&](int c, int s) {
        uint32_t kb = sb + AT_K + s * 8192;
        uint32_t vb = sb + AT_V + s * 8192;
#pragma unroll
        for (int l = 0; l < 2; l++) {
            int gi = tid + 256 * l;
            int row = gi >> 4, q = gi & 15;
            cpasync16(kb + stw[l], kg + (size_t)(c * 32 + row) * 2048 + q * 16);
            cpasync16(vb + stw[l], vg + (size_t)(c * 32 + row) * 2048 + q * 16);
        }
        if (tid < 8)
            cpasync16(sb + AT_MK + s * 128 + tid * 16,
                      (const char*)(mask + (size_t)b * M + c * 32) + tid * 16);
        asm volatile("cp.async.commit_group;" ::: "memory");
    };

    load_stage(0, 0);
    load_stage(1, 1);

    const uint32_t aswq = swz((wrp * 16 + (lane & 15)) * 128
                              + ((lane >> 4) << 4));
    uint32_t bswk[2];
#pragma unroll
    for (int hf = 0; hf < 2; hf++)
        bswk[hf] = swz((hf * 16 + (lane & 7) + ((lane >> 4) << 3)) * 128
                       + (((lane >> 3) & 1) << 4));
    const uint32_t vrow = ((lane & 7) + (((lane >> 3) & 1) << 3)) * 128;
    const uint32_t vcol = ((lane >> 4) << 4);
    const uint32_t swvr = swz(vrow);

    float O[16][4];
#pragma unroll
    for (int j = 0; j < 16; j++)
#pragma unroll
        for (int t = 0; t < 4; t++) O[j][t] = 0.f;
    float mi[2] = {-1e30f, -1e30f}, li[2] = {0.f, 0.f};
    const float scaling = 0.08838834764831845f;

    const int NCHA = M / 32;
    for (int c = 0; c < NCHA; c++) {
        if (c < NCHA - 2) asm volatile("cp.async.wait_group 1;" ::: "memory");
        else              asm volatile("cp.async.wait_group 0;" ::: "memory");
        __syncthreads();
        if (c + 2 < NCHA) load_stage(c + 2, (c + 2) % 3);

        const uint32_t Kb = sb + AT_K + (c % 3) * 8192;
        const uint32_t Vb = sb + AT_V + (c % 3) * 8192;
        const int* mk = (const int*)(dsm + AT_MK + (c % 3) * 128);

        // ---- S = Q . Ktile^T  (D = 128) ----
        float cS[4][4];
#pragma unroll
        for (int t = 0; t < 4; t++)
#pragma unroll
            for (int u = 0; u < 4; u++) cS[t][u] = 0.f;
#pragma unroll
        for (int kc = 0; kc < 2; kc++) {
#pragma unroll
            for (int ks = 0; ks < 4; ks++) {
                const uint32_t kb = ks << 5;
                uint32_t a[4], bb[2][4];
                ldsm_x4(a, sb + AT_Q + kc * 16384 + (aswq ^ kb));
#pragma unroll
                for (int hf = 0; hf < 2; hf++)
                    ldsm_x4(bb[hf], Kb + kc * 4096 + (bswk[hf] ^ kb));
#pragma unroll
                for (int hf = 0; hf < 2; hf++) {
                    mma_f16(cS[hf * 2 + 0], a, &bb[hf][0]);
                    mma_f16(cS[hf * 2 + 1], a, &bb[hf][2]);
                }
            }
        }

        // ---- softmax (warp-local rows) ----
#pragma unroll
        for (int t = 0; t < 4; t++) {
            int2 mv = *(const int2*)&mk[t * 8 + ((lane & 3) << 1)];
#pragma unroll
            for (int u = 0; u < 4; u++) {
                float s = cS[t][u] * scaling;
                int mkv = (u & 1) ? mv.y : mv.x;
                cS[t][u] = (mkv == 0) ? -1e9f : s;
            }
        }
        float tmax0 = -1e30f, tmax1 = -1e30f;
#pragma unroll
        for (int t = 0; t < 4; t++) {
            tmax0 = fmaxf(tmax0, fmaxf(cS[t][0], cS[t][1]));
            tmax1 = fmaxf(tmax1, fmaxf(cS[t][2], cS[t][3]));
        }
#pragma unroll
        for (int o = 1; o < 4; o <<= 1) {
            tmax0 = fmaxf(tmax0, __shfl_xor_sync(0xFFFFFFFFu, tmax0, o));
            tmax1 = fmaxf(tmax1, __shfl_xor_sync(0xFFFFFFFFu, tmax1, o));
        }
        float mn0 = fmaxf(mi[0], tmax0), mn1 = fmaxf(mi[1], tmax1);
        float al0 = __expf(mi[0] - mn0), al1 = __expf(mi[1] - mn1);
        mi[0] = mn0; mi[1] = mn1;

        float ps0 = 0.f, ps1 = 0.f;
#pragma unroll
        for (int t = 0; t < 4; t++) {
            cS[t][0] = __expf(cS[t][0] - mn0);
            cS[t][1] = __expf(cS[t][1] - mn0);
            cS[t][2] = __expf(cS[t][2] - mn1);
            cS[t][3] = __expf(cS[t][3] - mn1);
            ps0 += cS[t][0] + cS[t][1];
            ps1 += cS[t][2] + cS[t][3];
        }
#pragma unroll
        for (int o = 1; o < 4; o <<= 1) {
            ps0 += __shfl_xor_sync(0xFFFFFFFFu, ps0, o);
            ps1 += __shfl_xor_sync(0xFFFFFFFFu, ps1, o);
        }
        li[0] = li[0] * al0 + ps0;
        li[1] = li[1] * al1 + ps1;
#pragma unroll
        for (int j = 0; j < 16; j++) {
            O[j][0] *= al0; O[j][1] *= al0;
            O[j][2] *= al1; O[j][3] *= al1;
        }

        // pack P into A fragments (fp16)
        uint32_t ahh[2][4];
#pragma unroll
        for (int ks = 0; ks < 2; ks++) {
#pragma unroll
            for (int sub = 0; sub < 2; sub++) {
                int t = 2 * ks + sub;
                ahh[ks][sub * 2 + 0] = packh2(__float2half(cS[t][0]),
                                              __float2half(cS[t][1]));
                ahh[ks][sub * 2 + 1] = packh2(__float2half(cS[t][2]),
                                              __float2half(cS[t][3]));
            }
        }

        // ---- O += P . V ----
#pragma unroll
        for (int g = 0; g < 8; g++) {
            const int vch = g >> 2;
            const uint32_t colb = (g & 3) * 32 + vcol;
#pragma unroll
            for (int ks = 0; ks < 2; ks++) {
                uint32_t bv[4];
                uint32_t ro = (uint32_t)(ks * 16) * 128;
                ldsm_x4_t(bv, Vb + vch * 4096 + ro + (swvr ^ colb));
                mma_f16(O[2 * g + 0], ahh[ks], &bv[0]);
                mma_f16(O[2 * g + 1], ahh[ks], &bv[2]);
            }
        }
    }

    float inv0 = 1.0f / li[0], inv1 = 1.0f / li[1];
#pragma unroll
    for (int half_ = 0; half_ < 2; half_++) {
        float inv = half_ ? inv1 : inv0;
        int token = b * M + qrow0 + wrp * 16 + (lane >> 2) + half_ * 8;
        size_t rowbase = (size_t)token * 1024 + hd * 128 + ((lane & 3) << 1);
#pragma unroll
        for (int j = 0; j < 16; j++) {
            float v0 = O[j][half_ * 2 + 0] * inv;
            float v1 = O[j][half_ * 2 + 1] * inv;
            *(uint32_t*)(OB + rowbase + j * 8) = packh2(__float2half(v0),
                                                        __float2half(v1));
        }
    }
}

// ---------------------------------------------------------------------------
// Launch: R9 topology exactly (3 side streams, 7 events — proven clean).
// ---------------------------------------------------------------------------
extern "C" void kernel_launch(void* const* d_in, const int* in_sizes, int n_in,
                              void* d_out, int out_size)
{
    const float* query  = (const float*)d_in[0];
    const float* key    = (const float*)d_in[1];
    const int*   mask   = (const int*)d_in[2];
    // d_in[3] = value1, intentionally unused (matches reference)
    const float* value2 = (const float*)d_in[4];
    const float* Wq = (const float*)d_in[5];
    const float* bq = (const float*)d_in[6];
    const float* gq = (const float*)d_in[7];
    const float* betaq = (const float*)d_in[8];
    const float* Wk = (const float*)d_in[9];
    const float* bk = (const float*)d_in[10];
    const float* gk = (const float*)d_in[11];
    const float* betak = (const float*)d_in[12];
    const float* Wv = (const float*)d_in[13];
    const float* bv = (const float*)d_in[14];
    const float* gv = (const float*)d_in[15];
    const float* betav = (const float*)d_in[16];
    const float* Wm = (const float*)d_in[17];
    const float* bm = (const float*)d_in[18];

    const int B = in_sizes[3] / EDIM;   // value1 is [B, E]
    const int Ntok = in_sizes[2];       // mask is [B, M]
    const int M = Ntok / B;

    __half *aq, *ak, *av, *ao, *wq2, *wk2, *wv2, *wm2, *qp, *kp, *vp;
    cudaGetSymbolAddress((void**)&aq, g_aq);
    cudaGetSymbolAddress((void**)&ak, g_ak);
    cudaGetSymbolAddress((void**)&av, g_av);
    cudaGetSymbolAddress((void**)&ao, g_ao);
    cudaGetSymbolAddress((void**)&wq2, g_wq2);
    cudaGetSymbolAddress((void**)&wk2, g_wk2);
    cudaGetSymbolAddress((void**)&wv2, g_wv2);
    cudaGetSymbolAddress((void**)&wm2, g_wm2);
    cudaGetSymbolAddress((void**)&qp, g_qp);
    cudaGetSymbolAddress((void**)&kp, g_kp);
    cudaGetSymbolAddress((void**)&vp, g_vp);

    static cudaStream_t s2 = nullptr, s3 = nullptr, s4 = nullptr;
    static cudaEvent_t evRoot = nullptr, evK = nullptr, evV = nullptr,
                       evW = nullptr;
    if (!s2) {
        cudaStreamCreateWithFlags(&s2, cudaStreamNonBlocking);
        cudaStreamCreateWithFlags(&s3, cudaStreamNonBlocking);
        cudaStreamCreateWithFlags(&s4, cudaStreamNonBlocking);
        cudaEventCreateWithFlags(&evRoot, cudaEventDisableTiming);
        cudaEventCreateWithFlags(&evK, cudaEventDisableTiming);
        cudaEventCreateWithFlags(&evV, cudaEventDisableTiming);
        cudaEventCreateWithFlags(&evW, cudaEventDisableTiming);
        cudaFuncSetAttribute(gemm_tc<0>,
            cudaFuncAttributeMaxDynamicSharedMemorySize, GEMM_SMEM);
        cudaFuncSetAttribute(gemm_tc<1>,
            cudaFuncAttributeMaxDynamicSharedMemorySize, GEMM_SMEM);
        cudaFuncSetAttribute(attn_tc,
            cudaFuncAttributeMaxDynamicSharedMemorySize, AT_SMEM);
    }

    dim3 blk(256);
    dim3 gg(EDIM / 128, Ntok / 128);
    const int CAW = EDIM * EDIM / 2048;   // weight convert grid (512)
    const int CAA = Ntok * EDIM / 2048;   // activation convert grid (16384)

    // ---- fork ----
    cudaEventRecord(evRoot, 0);
    cudaStreamWaitEvent(s2, evRoot, 0);
    cudaStreamWaitEvent(s3, evRoot, 0);
    cudaStreamWaitEvent(s4, evRoot, 0);

    // Q chain (capture stream)
    convert1h<<<CAW, 256>>>(Wq, wq2);
    convert1h<<<CAA, 256>>>(query, aq);
    gemm_tc<1><<<gg, blk, GEMM_SMEM>>>(aq, wq2, bq, gq, betaq, qp);

    // K chain (s2)
    convert1h<<<CAW, 256, 0, s2>>>(Wk, wk2);
    convert1h<<<CAA, 256, 0, s2>>>(key, ak);
    gemm_tc<1><<<gg, blk, GEMM_SMEM, s2>>>(ak, wk2, bk, gk, betak, kp);

    // V chain (s3)
    convert1h<<<CAW, 256, 0, s3>>>(Wv, wv2);
    convert1h<<<CAA, 256, 0, s3>>>(value2, av);
    gemm_tc<1><<<gg, blk, GEMM_SMEM, s3>>>(av, wv2, bv, gv, betav, vp);

    // Wm convert (s4) — needed only by the final GEMM
    convert1h<<<CAW, 256, 0, s4>>>(Wm, wm2);

    // ---- join ----
    cudaEventRecord(evK, s2);
    cudaStreamWaitEvent(0, evK, 0);
    cudaEventRecord(evV, s3);
    cudaStreamWaitEvent(0, evV, 0);
    cudaEventRecord(evW, s4);
    cudaStreamWaitEvent(0, evW, 0);

    dim3 ga(M / 128, HEADS, B);
    attn_tc<<<ga, blk, AT_SMEM>>>(qp, kp, vp, mask, ao, M);

    gemm_tc<0><<<gg, blk, GEMM_SMEM>>>(ao, wm2, bm, nullptr, nullptr, d_out);
}